// round 7
// baseline (speedup 1.0000x reference)
#include <cuda_runtime.h>
#include <cstdint>
#include <math.h>

#define BB   256
#define SS   4096
#define VV   6
#define DD   32
#define HH   16
#define PADV 5
#define KK   614          // max(1, int(4096*0.15))
#define CL   4            // chunks (CTAs) per row
#define TPB  256
#define TOKC (SS / CL)    // 1024 tokens per chunk
#define NW   (TPB / 32)

// Single fused kernel. 4 CTAs per row; CTA (b,c) emits chunk c but redundantly
// counts the entire row (sibling chunks come from L2). No second launch, no
// cluster barrier, no atomics.
__global__ __launch_bounds__(TPB, 5) void fused_kernel(
    const int*   __restrict__ x,
    const float* __restrict__ emb,
    const float* __restrict__ sw1, const float* __restrict__ sb1,
    const float* __restrict__ sw2, const float* __restrict__ sb2,
    const float* __restrict__ aw1, const float* __restrict__ ab1,
    const float* __restrict__ aw2, const float* __restrict__ ab2,
    const float* __restrict__ cw1, const float* __restrict__ cb1,
    const float* __restrict__ cw2, const float* __restrict__ cb2,
    float* __restrict__ out_pred,
    float* __restrict__ out_top,
    float* __restrict__ out_sc)
{
    __shared__ float table[VV][DD];
    __shared__ float rbuf[VV][DD];
    __shared__ float hbuf[VV][HH];
    __shared__ float arow[VV][DD];
    __shared__ float sscore[VV];
    __shared__ int   warpsum[NW][VV];          // own-chunk per-warp -> exclusive prefix
    __shared__ unsigned long long osum[NW];    // other-chunk packed totals per warp
    __shared__ unsigned long long psum[NW];    // chunks<c packed totals per warp
    __shared__ int   cpre_sh[VV];              // tokens of vocab v in chunks < c
    __shared__ int   rowtot[VV];               // row totals per vocab
    __shared__ int   take[VV], obase[VV];
    __shared__ float pooled[DD];
    __shared__ float h2[HH];

    const int t    = threadIdx.x;
    const int lane = t & 31;
    const int warp = t >> 5;
    const int b    = blockIdx.x >> 2;
    const int c    = blockIdx.x & 3;

    // ---- issue all x loads early ----
    const int4* rowp = (const int4*)(x + (size_t)b * SS);
    const int4 xw = rowp[c * (TOKC / 4) + t];          // own chunk (emit)
    int4 xo[CL - 1];                                   // sibling chunks (count only)
    {
        int i = 0;
        #pragma unroll
        for (int r = 0; r < CL; ++r)
            if (r != c) xo[i++] = rowp[r * (TOKC / 4) + t];
    }

    // ---- MLP stage (vocab-level, redundant per CTA, weights L2-hot) ----
    if (t < VV * DD) {
        int v = t >> 5, i = t & 31;
        table[v][i] = (v == PADV) ? 0.0f : emb[v * DD + i];
    }
    __syncthreads();                                           // S1
    if (t < VV * DD) {
        int v = t >> 5, i = t & 31;
        float acc = ab1[i];
        #pragma unroll
        for (int d = 0; d < DD; ++d) acc += table[v][d] * aw1[d * DD + i];
        rbuf[v][i] = fmaxf(acc, 0.0f);
    }
    if (t < VV * HH) {
        int v = t >> 4, j = t & 15;
        float acc = sb1[j];
        #pragma unroll
        for (int d = 0; d < DD; ++d) acc += table[v][d] * sw1[d * HH + j];
        hbuf[v][j] = fmaxf(acc, 0.0f);
    }
    __syncthreads();                                           // S2
    if (t < VV * DD) {
        int v = t >> 5, i = t & 31;
        float acc = ab2[i];
        #pragma unroll
        for (int m = 0; m < DD; ++m) acc += rbuf[v][m] * aw2[m * DD + i];
        arow[v][i] = acc;
    }
    if (t >= 224 && t < 224 + VV) {
        int v = t - 224;
        float acc = sb2[0];
        #pragma unroll
        for (int j = 0; j < HH; ++j) acc += hbuf[v][j] * sw2[j];
        sscore[v] = 1.0f / (1.0f + expf(-acc));
    }

    // ---- counting (no shared deps; overlaps MLP latency) ----
    unsigned long long cpack =
        (1ull << (10 * xw.x)) + (1ull << (10 * xw.y)) +
        (1ull << (10 * xw.z)) + (1ull << (10 * xw.w));
    const unsigned long long own = cpack;

    unsigned long long opack = 0ull, ppack = 0ull;
    {
        int i = 0;
        #pragma unroll
        for (int r = 0; r < CL; ++r) {
            if (r == c) continue;
            const int4 w = xo[i++];
            unsigned long long p =
                (1ull << (10 * w.x)) + (1ull << (10 * w.y)) +
                (1ull << (10 * w.z)) + (1ull << (10 * w.w));
            opack += p;
            if (r < c) ppack += p;
        }
    }
    // warp inclusive scan of own-chunk counts (stability: ascending position)
    #pragma unroll
    for (int off = 1; off < 32; off <<= 1) {
        unsigned long long n = __shfl_up_sync(0xffffffffu, cpack, off);
        if (lane >= off) cpack += n;
    }
    // warp butterfly reduce of other/prefix counts
    #pragma unroll
    for (int off = 16; off > 0; off >>= 1) {
        opack += __shfl_xor_sync(0xffffffffu, opack, off);
        ppack += __shfl_xor_sync(0xffffffffu, ppack, off);
    }
    if (lane == 31) {
        #pragma unroll
        for (int v = 0; v < VV; ++v)
            warpsum[warp][v] = (int)((cpack >> (10 * v)) & 1023ull);
    }
    if (lane == 0) { osum[warp] = opack; psum[warp] = ppack; }
    __syncthreads();                                           // S3 (sscore/arow ready too)

    if (t < VV) {
        int run = 0;
        #pragma unroll
        for (int w = 0; w < NW; ++w) { int s = warpsum[w][t]; warpsum[w][t] = run; run += s; }
        int oth = 0, pre = 0;
        #pragma unroll
        for (int w = 0; w < NW; ++w) {
            oth += (int)((osum[w] >> (10 * t)) & 1023ull);
            pre += (int)((psum[w] >> (10 * t)) & 1023ull);
        }
        cpre_sh[t] = pre;
        rowtot[t]  = run + oth;
    }
    __syncthreads();                                           // S4

    if (t == 0) {
        // stable selection sort of 6 scores, descending (ties: lower vocab first)
        int order[VV];
        #pragma unroll
        for (int v = 0; v < VV; ++v) order[v] = v;
        for (int a = 0; a < VV; ++a) {
            int best = a;
            for (int q = a + 1; q < VV; ++q)
                if (sscore[order[q]] > sscore[order[best]]) best = q;
            int tmp = order[a]; order[a] = order[best]; order[best] = tmp;
        }
        int budget = KK, off = 0;
        #pragma unroll
        for (int r = 0; r < VV; ++r) {
            int v  = order[r];
            int tk = min(rowtot[v], budget);
            take[v]  = tk;
            obase[v] = off;
            off    += tk;
            budget -= tk;
        }
    }
    // scores output (needs only sscore, ready since S3)
    {
        float4 f;
        f.x = sscore[xw.x]; f.y = sscore[xw.y];
        f.z = sscore[xw.z]; f.w = sscore[xw.w];
        ((float4*)(out_sc + (size_t)b * SS + c * TOKC))[t] = f;
    }
    __syncthreads();                                           // S5

    // ---- emit top_idx (R3-style dynamic loop; stable within vocab) ----
    {
        const unsigned long long excl = cpack - own;
        int o[VV];
        #pragma unroll
        for (int v = 0; v < VV; ++v)
            o[v] = cpre_sh[v] + warpsum[warp][v] + (int)((excl >> (10 * v)) & 1023ull);

        float* trow = out_top + (size_t)b * KK;
        const int pbase = c * TOKC + t * 4;
        const int tok[4] = {xw.x, xw.y, xw.z, xw.w};
        #pragma unroll
        for (int j = 0; j < 4; ++j) {
            int v   = tok[j];
            int ord = o[v]++;
            if (ord < take[v])
                trow[obase[v] + ord] = (float)(pbase + j);
        }
    }

    // ---- classifier (chunk-0 CTA only) ----
    if (c == 0) {
        if (t < DD) {
            float acc = 0.0f;
            #pragma unroll
            for (int v = 0; v < VV; ++v) acc += (float)take[v] * arow[v][t];
            pooled[t] = acc * (1.0f / (float)KK);
        }
        __syncthreads();
        if (t < HH) {
            float acc = cb1[t];
            #pragma unroll
            for (int d = 0; d < DD; ++d) acc += pooled[d] * cw1[d * HH + t];
            h2[t] = fmaxf(acc, 0.0f);
        }
        __syncthreads();
        if (t == 0) {
            float acc = cb2[0];
            #pragma unroll
            for (int j = 0; j < HH; ++j) acc += h2[j] * cw2[j];
            out_pred[b] = 1.0f / (1.0f + expf(-acc));
        }
    }
}

extern "C" void kernel_launch(void* const* d_in, const int* in_sizes, int n_in,
                              void* d_out, int out_size) {
    const int*   x   = (const int*)  d_in[0];
    const float* emb = (const float*)d_in[1];
    const float* sw1 = (const float*)d_in[2];
    const float* sb1 = (const float*)d_in[3];
    const float* sw2 = (const float*)d_in[4];
    const float* sb2 = (const float*)d_in[5];
    const float* aw1 = (const float*)d_in[6];
    const float* ab1 = (const float*)d_in[7];
    const float* aw2 = (const float*)d_in[8];
    const float* ab2 = (const float*)d_in[9];
    const float* cw1 = (const float*)d_in[10];
    const float* cb1 = (const float*)d_in[11];
    const float* cw2 = (const float*)d_in[12];
    const float* cb2 = (const float*)d_in[13];

    float* out      = (float*)d_out;
    float* out_pred = out;
    float* out_top  = out + BB;
    float* out_sc   = out + BB + (size_t)BB * KK;

    fused_kernel<<<BB * CL, TPB>>>(x, emb, sw1, sb1, sw2, sb2,
                                   aw1, ab1, aw2, ab2,
                                   cw1, cb1, cw2, cb2,
                                   out_pred, out_top, out_sc);
}

// round 8
// speedup vs baseline: 2.1253x; 2.1253x over previous
#include <cuda_runtime.h>
#include <cstdint>
#include <math.h>

#define BB   256
#define SS   4096
#define VV   6
#define DD   32
#define HH   16
#define PADV 5
#define KK   614          // max(1, int(4096*0.15))
#define CL   4            // chunks per row (emit kernel)
#define TPB  256
#define TOKC (SS / CL)    // 1024 tokens per chunk
#define NW   (TPB / 32)

// Cross-kernel scratch
__device__ int   g_counts[BB][CL][VV];
__device__ float g_sscore[VV];
__device__ float g_arow[VV][DD];
__device__ int   g_order[VV];

// ---------------- K1: per-chunk vocab counts (half-row CTAs) + one MLP CTA ----------------
__global__ __launch_bounds__(TPB, 8) void count_kernel(
    const int*   __restrict__ x,
    const float* __restrict__ emb,
    const float* __restrict__ sw1, const float* __restrict__ sb1,
    const float* __restrict__ sw2, const float* __restrict__ sb2,
    const float* __restrict__ aw1, const float* __restrict__ ab1,
    const float* __restrict__ aw2, const float* __restrict__ ab2)
{
    const int t = threadIdx.x;

    // Signal PDL: dependent grid (emit) may start launching now; its
    // griddepcontrol.wait still blocks until this grid fully completes.
    asm volatile("griddepcontrol.launch_dependents;" ::: "memory");

    if (blockIdx.x < BB * 2) {
        // CTA covers half a row (2048 tokens); warp w covers 256 contiguous tokens.
        const int b    = blockIdx.x >> 1;
        const int half = blockIdx.x & 1;
        const int lane = t & 31;
        const int warp = t >> 5;
        const int4* base = (const int4*)(x + (size_t)b * SS + half * (SS / 2));

        const int4 a0 = base[warp * 64 + lane];
        const int4 a1 = base[warp * 64 + 32 + lane];

        unsigned long long cpack =
            (1ull << (10 * a0.x)) + (1ull << (10 * a0.y)) +
            (1ull << (10 * a0.z)) + (1ull << (10 * a0.w)) +
            (1ull << (10 * a1.x)) + (1ull << (10 * a1.y)) +
            (1ull << (10 * a1.z)) + (1ull << (10 * a1.w));
        #pragma unroll
        for (int off = 16; off > 0; off >>= 1)
            cpack += __shfl_xor_sync(0xffffffffu, cpack, off);

        __shared__ unsigned long long wtot[NW];
        if (lane == 0) wtot[warp] = cpack;
        __syncthreads();
        if (t < VV) {
            int s = 0;
            #pragma unroll
            for (int w = 0; w < 4; ++w) s += (int)((wtot[w] >> (10 * t)) & 1023ull);
            g_counts[b][2 * half][t] = s;
        } else if (t >= 32 && t < 32 + VV) {
            int v = t - 32, s = 0;
            #pragma unroll
            for (int w = 4; w < 8; ++w) s += (int)((wtot[w] >> (10 * v)) & 1023ull);
            g_counts[b][2 * half + 1][v] = s;
        }
        return;
    }

    // ---- single MLP CTA: vocab-level tables (row-independent) ----
    __shared__ float table[VV][DD];
    __shared__ float rbuf[VV][DD];
    __shared__ float hbuf[VV][HH];
    __shared__ float ssc[VV];

    if (t < VV * DD) {
        int v = t >> 5, i = t & 31;
        table[v][i] = (v == PADV) ? 0.0f : emb[v * DD + i];
    }
    __syncthreads();
    if (t < VV * DD) {
        int v = t >> 5, i = t & 31;
        float acc = ab1[i];
        #pragma unroll
        for (int d = 0; d < DD; ++d) acc += table[v][d] * aw1[d * DD + i];
        rbuf[v][i] = fmaxf(acc, 0.0f);
    }
    if (t < VV * HH) {
        int v = t >> 4, j = t & 15;
        float acc = sb1[j];
        #pragma unroll
        for (int d = 0; d < DD; ++d) acc += table[v][d] * sw1[d * HH + j];
        hbuf[v][j] = fmaxf(acc, 0.0f);
    }
    __syncthreads();
    if (t < VV * DD) {
        int v = t >> 5, i = t & 31;
        float acc = ab2[i];
        #pragma unroll
        for (int m = 0; m < DD; ++m) acc += rbuf[v][m] * aw2[m * DD + i];
        g_arow[v][i] = acc;
    }
    if (t >= 224 && t < 224 + VV) {
        int v = t - 224;
        float acc = sb2[0];
        #pragma unroll
        for (int j = 0; j < HH; ++j) acc += hbuf[v][j] * sw2[j];
        float s = 1.0f / (1.0f + expf(-acc));
        ssc[v] = s;
        g_sscore[v] = s;
    }
    __syncthreads();
    if (t == 0) {
        int order[VV];
        #pragma unroll
        for (int v = 0; v < VV; ++v) order[v] = v;
        for (int a = 0; a < VV; ++a) {
            int best = a;
            for (int q = a + 1; q < VV; ++q)
                if (ssc[order[q]] > ssc[order[best]]) best = q;
            int tmp = order[a]; order[a] = order[best]; order[best] = tmp;
        }
        #pragma unroll
        for (int a = 0; a < VV; ++a) g_order[a] = order[a];
    }
}

// ---------------- K2: scores + top_idx + pred (PDL consumer) ----------------
__global__ __launch_bounds__(TPB, 8) void emit_kernel(
    const int*   __restrict__ x,
    const float* __restrict__ cw1, const float* __restrict__ cb1,
    const float* __restrict__ cw2, const float* __restrict__ cb2,
    float* __restrict__ out_pred,
    float* __restrict__ out_top,
    float* __restrict__ out_sc)
{
    __shared__ float sscore[VV];
    __shared__ int   warpsum[NW][VV];
    __shared__ int   cpre_sh[VV], rowtot[VV];
    __shared__ int   take[VV];
    __shared__ unsigned long long takepack_sh, obasepack_sh;
    __shared__ float pooled[DD];
    __shared__ float h2[HH];

    const int t    = threadIdx.x;
    const int lane = t & 31;
    const int warp = t >> 5;
    const int b    = blockIdx.x >> 2;
    const int c    = blockIdx.x & 3;

    // ---------- PDL prologue: everything independent of K1 ----------
    const int4 xw = ((const int4*)(x + (size_t)b * SS + c * TOKC))[t];

    unsigned long long cpack =
        (1ull << (10 * xw.x)) + (1ull << (10 * xw.y)) +
        (1ull << (10 * xw.z)) + (1ull << (10 * xw.w));
    const unsigned long long own = cpack;
    #pragma unroll
    for (int off = 1; off < 32; off <<= 1) {
        unsigned long long n = __shfl_up_sync(0xffffffffu, cpack, off);
        if (lane >= off) cpack += n;
    }
    if (lane == 31) {
        #pragma unroll
        for (int v = 0; v < VV; ++v)
            warpsum[warp][v] = (int)((cpack >> (10 * v)) & 1023ull);
    }
    __syncthreads();                                           // S1

    if (t < VV) {
        int run = 0;
        #pragma unroll
        for (int w = 0; w < NW; ++w) { int s = warpsum[w][t]; warpsum[w][t] = run; run += s; }
    }

    // ---------- wait for K1 completion (counts, scores, order, arow) ----------
    asm volatile("griddepcontrol.wait;" ::: "memory");

    if (t < VV) {
        sscore[t] = g_sscore[t];
        int pre = 0, tot = 0;
        #pragma unroll
        for (int r = 0; r < CL; ++r) {
            int s = g_counts[b][r][t];
            tot += s;
            if (r < c) pre += s;
        }
        cpre_sh[t] = pre;
        rowtot[t]  = tot;
    }
    __syncthreads();                                           // S2

    if (t == 32) {
        int obase_l[VV];
        int budget = KK, off = 0;
        #pragma unroll
        for (int r = 0; r < VV; ++r) {
            int v  = g_order[r];
            int tk = min(rowtot[v], budget);
            take[v]    = tk;
            obase_l[v] = off;
            off    += tk;
            budget -= tk;
        }
        unsigned long long tp = 0ull, op = 0ull;
        #pragma unroll
        for (int v = 0; v < VV; ++v) {
            tp |= (unsigned long long)take[v]    << (10 * v);
            op |= (unsigned long long)obase_l[v] << (10 * v);
        }
        takepack_sh  = tp;
        obasepack_sh = op;
    }
    // scores output (sscore valid after S2)
    {
        float4 f;
        f.x = sscore[xw.x]; f.y = sscore[xw.y];
        f.z = sscore[xw.z]; f.w = sscore[xw.w];
        ((float4*)(out_sc + (size_t)b * SS + c * TOKC))[t] = f;
    }
    __syncthreads();                                           // S3

    // ---------- top_idx emit: register-packed ordinals, no local memory ----------
    {
        const unsigned long long excl = cpack - own;
        // running ordinal per vocab, 21-bit fields: pA = v0..2, pB = v3..5
        unsigned long long pA = 0ull, pB = 0ull;
        #pragma unroll
        for (int v = 0; v < 3; ++v)
            pA |= (unsigned long long)(cpre_sh[v] + warpsum[warp][v] +
                                       (int)((excl >> (10 * v)) & 1023ull)) << (21 * v);
        #pragma unroll
        for (int v = 3; v < VV; ++v)
            pB |= (unsigned long long)(cpre_sh[v] + warpsum[warp][v] +
                                       (int)((excl >> (10 * v)) & 1023ull)) << (21 * (v - 3));

        const unsigned long long takepack  = takepack_sh;
        const unsigned long long obasepack = obasepack_sh;
        float* trow = out_top + (size_t)b * KK;
        const int pbase = c * TOKC + t * 4;
        const int tok[4] = {xw.x, xw.y, xw.z, xw.w};
        #pragma unroll
        for (int j = 0; j < 4; ++j) {
            const int  v   = tok[j];
            const bool hi  = v >= 3;
            const int  f3  = hi ? v - 3 : v;
            const int  sh21 = f3 * 21;
            const unsigned long long cur = hi ? pB : pA;
            const int ord = (int)((cur >> sh21) & 0x1FFFFFull);
            const unsigned long long inc = 1ull << sh21;
            if (hi) pB += inc; else pA += inc;
            const int sh10 = v * 10;
            const int tk = (int)((takepack  >> sh10) & 1023ull);
            const int ob = (int)((obasepack >> sh10) & 1023ull);
            if (ord < tk)
                trow[ob + ord] = (float)(pbase + j);
        }
    }

    // ---------- classifier (chunk-0 CTA only) ----------
    if (c == 0) {
        if (t < DD) {
            float acc = 0.0f;
            #pragma unroll
            for (int v = 0; v < VV; ++v) acc += (float)take[v] * g_arow[v][t];
            pooled[t] = acc * (1.0f / (float)KK);
        }
        __syncthreads();
        if (t < HH) {
            float acc = cb1[t];
            #pragma unroll
            for (int d = 0; d < DD; ++d) acc += pooled[d] * cw1[d * HH + t];
            h2[t] = fmaxf(acc, 0.0f);
        }
        __syncthreads();
        if (t == 0) {
            float acc = cb2[0];
            #pragma unroll
            for (int j = 0; j < HH; ++j) acc += h2[j] * cw2[j];
            out_pred[b] = 1.0f / (1.0f + expf(-acc));
        }
    }
}

extern "C" void kernel_launch(void* const* d_in, const int* in_sizes, int n_in,
                              void* d_out, int out_size) {
    const int*   x   = (const int*)  d_in[0];
    const float* emb = (const float*)d_in[1];
    const float* sw1 = (const float*)d_in[2];
    const float* sb1 = (const float*)d_in[3];
    const float* sw2 = (const float*)d_in[4];
    const float* sb2 = (const float*)d_in[5];
    const float* aw1 = (const float*)d_in[6];
    const float* ab1 = (const float*)d_in[7];
    const float* aw2 = (const float*)d_in[8];
    const float* ab2 = (const float*)d_in[9];
    const float* cw1 = (const float*)d_in[10];
    const float* cb1 = (const float*)d_in[11];
    const float* cw2 = (const float*)d_in[12];
    const float* cb2 = (const float*)d_in[13];

    float* out      = (float*)d_out;
    float* out_pred = out;
    float* out_top  = out + BB;
    float* out_sc   = out + BB + (size_t)BB * KK;

    count_kernel<<<BB * 2 + 1, TPB>>>(x, emb, sw1, sb1, sw2, sb2,
                                      aw1, ab1, aw2, ab2);

    // Emit kernel with Programmatic Dependent Launch: overlaps its prologue
    // (x loads + scan) with count_kernel's execution.
    cudaLaunchConfig_t cfg = {};
    cfg.gridDim  = dim3(BB * CL);
    cfg.blockDim = dim3(TPB);
    cfg.dynamicSmemBytes = 0;
    cfg.stream   = 0;
    cudaLaunchAttribute attrs[1];
    attrs[0].id = cudaLaunchAttributeProgrammaticStreamSerialization;
    attrs[0].val.programmaticStreamSerializationAllowed = 1;
    cfg.attrs    = attrs;
    cfg.numAttrs = 1;
    cudaLaunchKernelEx(&cfg, emit_kernel, x, cw1, cb1, cw2, cb2,
                       out_pred, out_top, out_sc);
}

// round 12
// speedup vs baseline: 2.1912x; 1.0310x over previous
#include <cuda_runtime.h>
#include <cstdint>
#include <math.h>

#define BB   256
#define SS   4096
#define VV   6
#define DD   32
#define HH   16
#define PADV 5
#define KK   614          // max(1, int(4096*0.15))
#define TPB  1024
#define NW   (TPB / 32)   // 32 warps

// One CTA per row. 4 tokens/thread. Single kernel, no cross-CTA traffic.
__global__ __launch_bounds__(TPB, 1) void fused_kernel(
    const int*   __restrict__ x,
    const float* __restrict__ emb,
    const float* __restrict__ sw1, const float* __restrict__ sb1,
    const float* __restrict__ sw2, const float* __restrict__ sb2,
    const float* __restrict__ aw1, const float* __restrict__ ab1,
    const float* __restrict__ aw2, const float* __restrict__ ab2,
    const float* __restrict__ cw1, const float* __restrict__ cb1,
    const float* __restrict__ cw2, const float* __restrict__ cb2,
    float* __restrict__ out_pred,
    float* __restrict__ out_top,
    float* __restrict__ out_sc)
{
    __shared__ float table[VV][DD];
    __shared__ float rbuf[VV][DD];
    __shared__ float hbuf[VV][HH];
    __shared__ float arow[VV][DD];
    __shared__ float sscore[VV];
    __shared__ unsigned long long wtot[NW];          // per-warp packed totals (6x10-bit)
    __shared__ unsigned long long exclA[NW];         // cross-warp excl prefix, v0..2 (21-bit)
    __shared__ unsigned long long exclB[NW];         // cross-warp excl prefix, v3..5 (21-bit)
    __shared__ unsigned long long tp_sh, op_sh;      // take/obase packs (6x10-bit)

    const int t    = threadIdx.x;
    const int lane = t & 31;
    const int warp = t >> 5;
    const int b    = blockIdx.x;

    // ---- issue x load early: 4 contiguous tokens per thread, coalesced ----
    const int4 xw = ((const int4*)(x + (size_t)b * SS))[t];

    // ---- MLP stage 1: table = emb with PAD row zeroed ----
    if (t < VV * DD) {
        int v = t >> 5, i = t & 31;
        table[v][i] = (v == PADV) ? 0.0f : emb[v * DD + i];
    }
    __syncthreads();                                           // S1

    // ---- MLP hidden layers ----
    if (t < VV * DD) {
        int v = t >> 5, i = t & 31;
        float acc = ab1[i];
        #pragma unroll
        for (int d = 0; d < DD; ++d) acc += table[v][d] * aw1[d * DD + i];
        rbuf[v][i] = fmaxf(acc, 0.0f);
    }
    if (t < VV * HH) {
        int v = t >> 4, j = t & 15;
        float acc = sb1[j];
        #pragma unroll
        for (int d = 0; d < DD; ++d) acc += table[v][d] * sw1[d * HH + j];
        hbuf[v][j] = fmaxf(acc, 0.0f);
    }

    // ---- counting: packed 6x10-bit counts + warp inclusive scan (overlaps MLP) ----
    unsigned long long cpack =
        (1ull << (10 * xw.x)) + (1ull << (10 * xw.y)) +
        (1ull << (10 * xw.z)) + (1ull << (10 * xw.w));
    const unsigned long long own = cpack;
    #pragma unroll
    for (int off = 1; off < 32; off <<= 1) {
        unsigned long long n = __shfl_up_sync(0xffffffffu, cpack, off);
        if (lane >= off) cpack += n;
    }
    if (lane == 31) wtot[warp] = cpack;                // warp totals, fields <=128
    __syncthreads();                                           // S2

    // ---- MLP output layers ----
    if (t < VV * DD) {
        int v = t >> 5, i = t & 31;
        float acc = ab2[i];
        #pragma unroll
        for (int m = 0; m < DD; ++m) acc += rbuf[v][m] * aw2[m * DD + i];
        arow[v][i] = acc;
    }
    if (t >= 224 && t < 224 + VV) {
        int v = t - 224;
        float acc = sb2[0];
        #pragma unroll
        for (int j = 0; j < HH; ++j) acc += hbuf[v][j] * sw2[j];
        sscore[v] = 1.0f / (1.0f + expf(-acc));
    }
    __syncthreads();                                           // S3

    // ---- warp 0: cross-warp scan (21-bit fields) + rank + budget, all in regs ----
    unsigned long long tp = 0ull, op = 0ull;           // take/obase packs (warp0 regs)
    if (warp == 0) {
        const unsigned long long w64 = wtot[lane];
        const unsigned long long a0 =  (w64        & 1023ull)        |
                                      (((w64 >> 10) & 1023ull) << 21) |
                                      (((w64 >> 20) & 1023ull) << 42);
        const unsigned long long b0 = ((w64 >> 30) & 1023ull)        |
                                      (((w64 >> 40) & 1023ull) << 21) |
                                      (((w64 >> 50) & 1023ull) << 42);
        unsigned long long ia = a0, ib = b0;
        #pragma unroll
        for (int off = 1; off < 32; off <<= 1) {
            unsigned long long na = __shfl_up_sync(0xffffffffu, ia, off);
            unsigned long long nb = __shfl_up_sync(0xffffffffu, ib, off);
            if (lane >= off) { ia += na; ib += nb; }
        }
        exclA[lane] = ia - a0;
        exclB[lane] = ib - b0;
        const unsigned long long ta = __shfl_sync(0xffffffffu, ia, 31);
        const unsigned long long tb = __shfl_sync(0xffffffffu, ib, 31);

        // row totals per vocab (static extraction)
        int rt[VV];
        rt[0] = (int)( ta        & 0x1FFFFFull);
        rt[1] = (int)((ta >> 21) & 0x1FFFFFull);
        rt[2] = (int)((ta >> 42) & 0x1FFFFFull);
        rt[3] = (int)( tb        & 0x1FFFFFull);
        rt[4] = (int)((tb >> 21) & 0x1FFFFFull);
        rt[5] = (int)((tb >> 42) & 0x1FFFFFull);

        float sc[VV];
        #pragma unroll
        for (int v = 0; v < VV; ++v) sc[v] = sscore[v];

        // static pairwise rank: descending score, ties -> lower vocab first
        int rnk[VV];
        #pragma unroll
        for (int v = 0; v < VV; ++v) {
            int r = 0;
            #pragma unroll
            for (int u = 0; u < VV; ++u)
                r += (sc[u] > sc[v]) || (sc[u] == sc[v] && u < v);
            rnk[v] = r;
        }
        // budget split in rank order (static select loops; dynamic shifts only)
        int budget = KK, off = 0;
        #pragma unroll
        for (int r = 0; r < VV; ++r) {
            int vsel = 0, tot = 0;
            #pragma unroll
            for (int v = 0; v < VV; ++v)
                if (rnk[v] == r) { vsel = v; tot = rt[v]; }
            int tk = min(tot, budget);
            tp |= (unsigned long long)tk  << (10 * vsel);
            op |= (unsigned long long)off << (10 * vsel);
            off    += tk;
            budget -= tk;
        }
        if (lane == 0) { tp_sh = tp; op_sh = op; }
    }
    __syncthreads();                                           // S4

    // ---- scores output (coalesced float4) ----
    {
        float4 f;
        f.x = sscore[xw.x]; f.y = sscore[xw.y];
        f.z = sscore[xw.z]; f.w = sscore[xw.w];
        ((float4*)(out_sc + (size_t)b * SS))[t] = f;
    }

    // ---- emit top_idx: register-packed ordinals (21-bit fields) ----
    {
        const unsigned long long intra = cpack - own;  // intra-warp excl, 10-bit fields
        const unsigned long long iA =  (intra        & 1023ull)        |
                                      (((intra >> 10) & 1023ull) << 21) |
                                      (((intra >> 20) & 1023ull) << 42);
        const unsigned long long iB = ((intra >> 30) & 1023ull)        |
                                      (((intra >> 40) & 1023ull) << 21) |
                                      (((intra >> 50) & 1023ull) << 42);
        unsigned long long pA = exclA[warp] + iA;
        unsigned long long pB = exclB[warp] + iB;
        const unsigned long long takepack  = tp_sh;
        const unsigned long long obasepack = op_sh;
        float* trow = out_top + (size_t)b * KK;
        const int pbase = t * 4;
        const int tok[4] = {xw.x, xw.y, xw.z, xw.w};
        #pragma unroll
        for (int j = 0; j < 4; ++j) {
            const int  v    = tok[j];
            const bool hi   = v >= 3;
            const int  sh21 = (hi ? v - 3 : v) * 21;
            const unsigned long long cur = hi ? pB : pA;
            const int  ord  = (int)((cur >> sh21) & 0x1FFFFFull);
            const unsigned long long inc = 1ull << sh21;
            if (hi) pB += inc; else pA += inc;
            const int sh10 = v * 10;
            const int tk = (int)((takepack  >> sh10) & 1023ull);
            const int ob = (int)((obasepack >> sh10) & 1023ull);
            if (ord < tk)
                trow[ob + ord] = (float)(pbase + j);
        }
    }

    // ---- classifier: warp 0 only, shuffle-based, no extra barriers ----
    if (warp == 0) {
        float pooled = 0.0f;
        #pragma unroll
        for (int v = 0; v < VV; ++v)
            pooled += (float)((int)((tp >> (10 * v)) & 1023ull)) * arow[v][lane];
        pooled *= (1.0f / (float)KK);

        float h = (lane < HH) ? cb1[lane] : 0.0f;
        #pragma unroll
        for (int d = 0; d < DD; ++d) {
            const float p = __shfl_sync(0xffffffffu, pooled, d);
            if (lane < HH) h += p * cw1[d * HH + lane];
        }
        h = fmaxf(h, 0.0f);
        float contrib = (lane < HH) ? h * cw2[lane] : 0.0f;
        #pragma unroll
        for (int off = 16; off > 0; off >>= 1)
            contrib += __shfl_xor_sync(0xffffffffu, contrib, off);
        if (lane == 0)
            out_pred[b] = 1.0f / (1.0f + expf(-(contrib + cb2[0])));
    }
}

extern "C" void kernel_launch(void* const* d_in, const int* in_sizes, int n_in,
                              void* d_out, int out_size) {
    const int*   x   = (const int*)  d_in[0];
    const float* emb = (const float*)d_in[1];
    const float* sw1 = (const float*)d_in[2];
    const float* sb1 = (const float*)d_in[3];
    const float* sw2 = (const float*)d_in[4];
    const float* sb2 = (const float*)d_in[5];
    const float* aw1 = (const float*)d_in[6];
    const float* ab1 = (const float*)d_in[7];
    const float* aw2 = (const float*)d_in[8];
    const float* ab2 = (const float*)d_in[9];
    const float* cw1 = (const float*)d_in[10];
    const float* cb1 = (const float*)d_in[11];
    const float* cw2 = (const float*)d_in[12];
    const float* cb2 = (const float*)d_in[13];

    float* out      = (float*)d_out;
    float* out_pred = out;
    float* out_top  = out + BB;
    float* out_sc   = out + BB + (size_t)BB * KK;

    fused_kernel<<<BB, TPB>>>(x, emb, sw1, sb1, sw2, sb2,
                              aw1, ab1, aw2, ab2,
                              cw1, cb1, cw2, cb2,
                              out_pred, out_top, out_sc);
}